// round 1
// baseline (speedup 1.0000x reference)
#include <cuda_runtime.h>
#include <cuda_bf16.h>
#include <cstddef>

// ---------------- problem constants ----------------
#define D    512
#define H    8
#define DK   64
#define TT   128          // seq len (S == T == 128)
#define BBATCH 8
#define NL   6
#define VV   32000
#define FF   2048
#define MROWS (BBATCH*TT) // 1024 token rows

// ---------------- scratch (device globals; no allocation allowed) ----------------
__device__ float g_x  [MROWS*D];
__device__ float g_h  [MROWS*D];
__device__ float g_q  [MROWS*D];
__device__ float g_k  [MROWS*D];
__device__ float g_v  [MROWS*D];
__device__ float g_ao [MROWS*D];
__device__ float g_mem[MROWS*D];
__device__ float g_sc [BBATCH*H*TT*TT];
__device__ float g_ffn[MROWS*FF];

// ---------------- embedding: tok_emb[tok] + pos_emb[pos] ----------------
__global__ void embed_kernel(const int* __restrict__ tok,
                             const float* __restrict__ tok_emb,
                             const float* __restrict__ pos_emb,
                             float* __restrict__ out) {
    int idx = blockIdx.x * blockDim.x + threadIdx.x;
    if (idx >= MROWS * D) return;
    int row = idx / D, d = idx % D;
    int t = row % TT;
    out[idx] = tok_emb[(size_t)tok[row] * D + d] + pos_emb[(size_t)t * D + d];
}

// ---------------- layernorm (eps = 1e-6) ----------------
__global__ void ln_kernel(const float* __restrict__ x,
                          const float* __restrict__ g,
                          const float* __restrict__ b,
                          float* __restrict__ out) {
    int row = blockIdx.x;
    const float* xr = x + (size_t)row * D;
    __shared__ float sh[256];
    int tid = threadIdx.x;

    float s = 0.f;
    for (int i = tid; i < D; i += 256) s += xr[i];
    sh[tid] = s; __syncthreads();
    for (int o = 128; o; o >>= 1) { if (tid < o) sh[tid] += sh[tid + o]; __syncthreads(); }
    float mu = sh[0] * (1.f / D);
    __syncthreads();

    float v = 0.f;
    for (int i = tid; i < D; i += 256) { float dd = xr[i] - mu; v += dd * dd; }
    sh[tid] = v; __syncthreads();
    for (int o = 128; o; o >>= 1) { if (tid < o) sh[tid] += sh[tid + o]; __syncthreads(); }
    float inv = rsqrtf(sh[0] * (1.f / D) + 1e-6f);

    for (int i = tid; i < D; i += 256)
        out[(size_t)row * D + i] = (xr[i] - mu) * inv * g[i] + b[i];
}

// ---------------- tiled fp32 GEMM: C = op(A@B) [+bias] [relu] [+res] ----------------
// A: [M,K] row-major. TB==0: B is [K,N] row-major. TB==1: B is [N,K] row-major (NT).
// All of M,N divisible by 64; K divisible by 16 in this problem -> no bounds checks.
template<int TB>
__global__ void gemm_kernel(const float* __restrict__ A, const float* __restrict__ B,
                            const float* __restrict__ bias, const float* __restrict__ res,
                            float* __restrict__ C, int M, int N, int K, int relu) {
    __shared__ float As[16][68];
    __shared__ float Bs[16][68];
    int tid = threadIdx.x;           // 256 threads
    int m0 = blockIdx.y * 64, n0 = blockIdx.x * 64;
    int tr = (tid >> 4) << 2;        // 0..60
    int tc = (tid & 15) << 2;        // 0..60
    float acc[4][4] = {};

    for (int k0 = 0; k0 < K; k0 += 16) {
        {   // A tile 64x16, float4 per thread
            int r = tid >> 2, kq = (tid & 3) << 2;
            float4 a4 = *reinterpret_cast<const float4*>(A + (size_t)(m0 + r) * K + k0 + kq);
            As[kq + 0][r] = a4.x; As[kq + 1][r] = a4.y;
            As[kq + 2][r] = a4.z; As[kq + 3][r] = a4.w;
        }
        if (TB == 0) {
            int kk = tid >> 4, cq = (tid & 15) << 2;
            float4 b4 = *reinterpret_cast<const float4*>(B + (size_t)(k0 + kk) * N + n0 + cq);
            Bs[kk][cq + 0] = b4.x; Bs[kk][cq + 1] = b4.y;
            Bs[kk][cq + 2] = b4.z; Bs[kk][cq + 3] = b4.w;
        } else {
            int col = tid >> 2, kq = (tid & 3) << 2;
            float4 b4 = *reinterpret_cast<const float4*>(B + (size_t)(n0 + col) * K + k0 + kq);
            Bs[kq + 0][col] = b4.x; Bs[kq + 1][col] = b4.y;
            Bs[kq + 2][col] = b4.z; Bs[kq + 3][col] = b4.w;
        }
        __syncthreads();
        #pragma unroll
        for (int kk = 0; kk < 16; kk++) {
            float a[4], b[4];
            #pragma unroll
            for (int i = 0; i < 4; i++) a[i] = As[kk][tr + i];
            #pragma unroll
            for (int j = 0; j < 4; j++) b[j] = Bs[kk][tc + j];
            #pragma unroll
            for (int i = 0; i < 4; i++)
                #pragma unroll
                for (int j = 0; j < 4; j++) acc[i][j] += a[i] * b[j];
        }
        __syncthreads();
    }

    #pragma unroll
    for (int i = 0; i < 4; i++) {
        int m = m0 + tr + i;
        #pragma unroll
        for (int j = 0; j < 4; j++) {
            int n = n0 + tc + j;
            float val = acc[i][j];
            if (bias) val += bias[n];
            if (relu) val = fmaxf(val, 0.f);
            if (res)  val += res[(size_t)m * N + n];
            C[(size_t)m * N + n] = val;
        }
    }
}

// ---------------- attention scores + softmax ----------------
// grid: B*H*T blocks, 128 threads (one per key). Q,K in [B*T, D] layout (head h at cols h*DK..).
// mask: key masked if toks[b*T+k]==PAD(1), or (causal && k>q).
__global__ void attn_kernel(const float* __restrict__ Q, const float* __restrict__ Kp,
                            const int* __restrict__ toks, int causal,
                            float* __restrict__ scores) {
    int blk = blockIdx.x;
    int q = blk % TT;
    int h = (blk / TT) % H;
    int b = blk / (TT * H);
    int k = threadIdx.x;

    const float* qv = Q + (size_t)(b * TT + q) * D + h * DK;
    const float* kv = Kp + (size_t)(b * TT + k) * D + h * DK;
    float s = 0.f;
    #pragma unroll
    for (int d = 0; d < DK; d++) s += qv[d] * kv[d];
    s *= 0.125f;  // 1/sqrt(64)

    bool masked = (toks[b * TT + k] == 1) || (causal && k > q);
    if (masked) s = -1e30f;

    __shared__ float sh[TT];
    sh[k] = s; __syncthreads();
    for (int o = 64; o; o >>= 1) { if (k < o) sh[k] = fmaxf(sh[k], sh[k + o]); __syncthreads(); }
    float mx = sh[0]; __syncthreads();

    float e = expf(s - mx);
    sh[k] = e; __syncthreads();
    for (int o = 64; o; o >>= 1) { if (k < o) sh[k] += sh[k + o]; __syncthreads(); }
    float sum = sh[0];

    scores[(size_t)blk * TT + k] = e / sum;
}

// ---------------- out[b,q,h*DK+d] = sum_k a[b,h,q,k] * V[b,k,h*DK+d] ----------------
// grid: B*T blocks, D threads.
__global__ void av_kernel(const float* __restrict__ scores, const float* __restrict__ Vp,
                          float* __restrict__ out) {
    int row = blockIdx.x;            // b*T + q
    int b = row / TT, q = row % TT;
    int t = threadIdx.x;             // h*DK + d
    int h = t / DK;
    const float* a = scores + (size_t)((b * H + h) * TT + q) * TT;
    float acc = 0.f;
    #pragma unroll 4
    for (int k = 0; k < TT; k++)
        acc += a[k] * Vp[(size_t)(b * TT + k) * D + t];
    out[(size_t)row * D + t] = acc;
}

// ---------------- in-place log_softmax over V per row ----------------
__global__ void logsoftmax_kernel(float* __restrict__ logits) {
    int row = blockIdx.x;
    float* x = logits + (size_t)row * VV;
    __shared__ float sh[256];
    int tid = threadIdx.x;

    float mx = -1e30f;
    for (int i = tid; i < VV; i += 256) mx = fmaxf(mx, x[i]);
    sh[tid] = mx; __syncthreads();
    for (int o = 128; o; o >>= 1) { if (tid < o) sh[tid] = fmaxf(sh[tid], sh[tid + o]); __syncthreads(); }
    float M = sh[0]; __syncthreads();

    float s = 0.f;
    for (int i = tid; i < VV; i += 256) s += expf(x[i] - M);
    sh[tid] = s; __syncthreads();
    for (int o = 128; o; o >>= 1) { if (tid < o) sh[tid] += sh[tid + o]; __syncthreads(); }
    float lse = M + logf(sh[0]);

    for (int i = tid; i < VV; i += 256) x[i] -= lse;
}

// ---------------- host orchestration ----------------
static inline void launch_gemm(const float* A, const float* B, const float* bias,
                               const float* res, float* C, int M, int N, int K,
                               int relu, bool transb) {
    dim3 grid(N / 64, M / 64);
    if (transb) gemm_kernel<1><<<grid, 256>>>(A, B, bias, res, C, M, N, K, relu);
    else        gemm_kernel<0><<<grid, 256>>>(A, B, bias, res, C, M, N, K, relu);
}

extern "C" void kernel_launch(void* const* d_in, const int* in_sizes, int n_in,
                              void* d_out, int out_size) {
    const int*   src        = (const int*)  d_in[0];
    const int*   tgt        = (const int*)  d_in[1];
    const float* tok_emb    = (const float*)d_in[2];
    const float* pos_emb    = (const float*)d_in[3];
    const float* enc_attn_w = (const float*)d_in[4];   // [6,4,D,D]
    const float* enc_attn_b = (const float*)d_in[5];   // [6,4,D]
    const float* enc_ffn_w1 = (const float*)d_in[6];   // [6,D,FF]
    const float* enc_ffn_b1 = (const float*)d_in[7];   // [6,FF]
    const float* enc_ffn_w2 = (const float*)d_in[8];   // [6,FF,D]
    const float* enc_ffn_b2 = (const float*)d_in[9];   // [6,D]
    const float* enc_ln     = (const float*)d_in[10];  // [6,2,2,D]
    const float* enc_fln    = (const float*)d_in[11];  // [2,D]
    const float* dec_attn_w = (const float*)d_in[12];  // [6,8,D,D]
    const float* dec_attn_b = (const float*)d_in[13];  // [6,8,D]
    const float* dec_ffn_w1 = (const float*)d_in[14];
    const float* dec_ffn_b1 = (const float*)d_in[15];
    const float* dec_ffn_w2 = (const float*)d_in[16];
    const float* dec_ffn_b2 = (const float*)d_in[17];
    const float* dec_ln     = (const float*)d_in[18];  // [6,3,2,D]
    const float* dec_fln    = (const float*)d_in[19];  // [2,D]
    float* out = (float*)d_out;                        // [1024, 32000]

    float *x, *h, *q, *k, *v, *ao, *mem, *sc, *ffn;
    cudaGetSymbolAddress((void**)&x,   g_x);
    cudaGetSymbolAddress((void**)&h,   g_h);
    cudaGetSymbolAddress((void**)&q,   g_q);
    cudaGetSymbolAddress((void**)&k,   g_k);
    cudaGetSymbolAddress((void**)&v,   g_v);
    cudaGetSymbolAddress((void**)&ao,  g_ao);
    cudaGetSymbolAddress((void**)&mem, g_mem);
    cudaGetSymbolAddress((void**)&sc,  g_sc);
    cudaGetSymbolAddress((void**)&ffn, g_ffn);

    const size_t DD = (size_t)D * D;

    // ================= encoder =================
    embed_kernel<<<(MROWS * D + 255) / 256, 256>>>(src, tok_emb, pos_emb, x);
    for (int i = 0; i < NL; i++) {
        const float* W   = enc_attn_w + (size_t)i * 4 * DD;
        const float* Wb  = enc_attn_b + (size_t)i * 4 * D;
        const float* lnp = enc_ln + (size_t)i * 4 * D;   // [2 sublayers][2][D]

        ln_kernel<<<MROWS, 256>>>(x, lnp, lnp + D, h);
        launch_gemm(h, W,          Wb,         nullptr, q, MROWS, D, D, 0, false);
        launch_gemm(h, W + DD,     Wb + D,     nullptr, k, MROWS, D, D, 0, false);
        launch_gemm(h, W + 2 * DD, Wb + 2 * D, nullptr, v, MROWS, D, D, 0, false);
        attn_kernel<<<BBATCH * H * TT, TT>>>(q, k, src, 0, sc);
        av_kernel<<<MROWS, D>>>(sc, v, ao);
        launch_gemm(ao, W + 3 * DD, Wb + 3 * D, x, x, MROWS, D, D, 0, false);

        ln_kernel<<<MROWS, 256>>>(x, lnp + 2 * D, lnp + 3 * D, h);
        launch_gemm(h, enc_ffn_w1 + (size_t)i * D * FF, enc_ffn_b1 + (size_t)i * FF,
                    nullptr, ffn, MROWS, FF, D, 1, false);
        launch_gemm(ffn, enc_ffn_w2 + (size_t)i * FF * D, enc_ffn_b2 + (size_t)i * D,
                    x, x, MROWS, D, FF, 0, false);
    }
    ln_kernel<<<MROWS, 256>>>(x, enc_fln, enc_fln + D, mem);

    // ================= decoder =================
    embed_kernel<<<(MROWS * D + 255) / 256, 256>>>(tgt, tok_emb, pos_emb, x);
    for (int i = 0; i < NL; i++) {
        const float* W   = dec_attn_w + (size_t)i * 8 * DD;
        const float* Wb  = dec_attn_b + (size_t)i * 8 * D;
        const float* lnp = dec_ln + (size_t)i * 6 * D;   // [3 sublayers][2][D]

        // self-attention (causal + tgt pad)
        ln_kernel<<<MROWS, 256>>>(x, lnp, lnp + D, h);
        launch_gemm(h, W,          Wb,         nullptr, q, MROWS, D, D, 0, false);
        launch_gemm(h, W + DD,     Wb + D,     nullptr, k, MROWS, D, D, 0, false);
        launch_gemm(h, W + 2 * DD, Wb + 2 * D, nullptr, v, MROWS, D, D, 0, false);
        attn_kernel<<<BBATCH * H * TT, TT>>>(q, k, tgt, 1, sc);
        av_kernel<<<MROWS, D>>>(sc, v, ao);
        launch_gemm(ao, W + 3 * DD, Wb + 3 * D, x, x, MROWS, D, D, 0, false);

        // cross-attention (keys/values from encoder memory, src pad mask)
        ln_kernel<<<MROWS, 256>>>(x, lnp + 2 * D, lnp + 3 * D, h);
        launch_gemm(h,   W + 4 * DD, Wb + 4 * D, nullptr, q, MROWS, D, D, 0, false);
        launch_gemm(mem, W + 5 * DD, Wb + 5 * D, nullptr, k, MROWS, D, D, 0, false);
        launch_gemm(mem, W + 6 * DD, Wb + 6 * D, nullptr, v, MROWS, D, D, 0, false);
        attn_kernel<<<BBATCH * H * TT, TT>>>(q, k, src, 0, sc);
        av_kernel<<<MROWS, D>>>(sc, v, ao);
        launch_gemm(ao, W + 7 * DD, Wb + 7 * D, x, x, MROWS, D, D, 0, false);

        // FFN
        ln_kernel<<<MROWS, 256>>>(x, lnp + 4 * D, lnp + 5 * D, h);
        launch_gemm(h, dec_ffn_w1 + (size_t)i * D * FF, dec_ffn_b1 + (size_t)i * FF,
                    nullptr, ffn, MROWS, FF, D, 1, false);
        launch_gemm(ffn, dec_ffn_w2 + (size_t)i * FF * D, dec_ffn_b2 + (size_t)i * D,
                    x, x, MROWS, D, FF, 0, false);
    }
    ln_kernel<<<MROWS, 256>>>(x, dec_fln, dec_fln + D, h);

    // ============ generator: tied projection + log_softmax ============
    launch_gemm(h, tok_emb, nullptr, nullptr, out, MROWS, VV, D, 0, true);  // NT
    logsoftmax_kernel<<<MROWS, 256>>>(out);
}

// round 2
// speedup vs baseline: 1.6127x; 1.6127x over previous
#include <cuda_runtime.h>
#include <cuda_bf16.h>
#include <mma.h>
#include <cstddef>

using namespace nvcuda;
typedef __nv_bfloat16 bf16;

// ---------------- problem constants ----------------
#define D    512
#define H    8
#define DK   64
#define TT   128
#define BBATCH 8
#define NL   6
#define VV   32000
#define FF   2048
#define MROWS (BBATCH*TT)   // 1024
#define MD   (MROWS*D)

// weight bf16 pool offsets
#define N_EA  (NL*4*D*D)        // 6291456
#define N_EF1 (NL*D*FF)         // 6291456
#define N_EF2 (NL*FF*D)         // 6291456
#define N_DA  (NL*8*D*D)        // 12582912
#define N_DF1 (NL*D*FF)
#define N_DF2 (NL*FF*D)
#define N_EMB (VV*D)            // 16384000
#define OFF_EA   0
#define OFF_EF1  (OFF_EA + N_EA)
#define OFF_EF2  (OFF_EF1 + N_EF1)
#define OFF_DA   (OFF_EF2 + N_EF2)
#define OFF_DF1  (OFF_DA + N_DA)
#define OFF_DF2  (OFF_DF1 + N_DF1)
#define OFF_EMB  (OFF_DF2 + N_DF2)
#define WPOOL_N  (OFF_EMB + N_EMB)   // 60424192

// ---------------- scratch ----------------
__device__ float g_x  [MD];
__device__ float g_qkv[3*MD];
__device__ float g_sc [BBATCH*H*TT*TT];
__device__ bf16  g_hb [MD];
__device__ bf16  g_aob[MD];
__device__ bf16  g_memb[MD];
__device__ bf16  g_ffnb[MROWS*FF];
__device__ bf16  g_wpool[WPOOL_N];

// ---------------- fp32 -> bf16 conversion ----------------
__global__ void f2b_kernel(const float* __restrict__ s, bf16* __restrict__ d, int n4) {
    int i = blockIdx.x * blockDim.x + threadIdx.x;
    if (i >= n4) return;
    float4 v = reinterpret_cast<const float4*>(s)[i];
    __nv_bfloat162* o = reinterpret_cast<__nv_bfloat162*>(d) + 2 * i;
    o[0] = __floats2bfloat162_rn(v.x, v.y);
    o[1] = __floats2bfloat162_rn(v.z, v.w);
}

// ---------------- embedding ----------------
__global__ void embed_kernel(const int* __restrict__ tok,
                             const float* __restrict__ tok_emb,
                             const float* __restrict__ pos_emb,
                             float* __restrict__ out) {
    int idx = blockIdx.x * blockDim.x + threadIdx.x;
    if (idx >= MROWS * D) return;
    int row = idx / D, d = idx % D;
    int t = row % TT;
    out[idx] = tok_emb[(size_t)tok[row] * D + d] + pos_emb[(size_t)t * D + d];
}

// ---------------- layernorm -> bf16 ----------------
__global__ void ln_kernel(const float* __restrict__ x,
                          const float* __restrict__ g,
                          const float* __restrict__ b,
                          bf16* __restrict__ out) {
    int row = blockIdx.x;
    const float* xr = x + (size_t)row * D;
    __shared__ float sh[256];
    int tid = threadIdx.x;

    float s = 0.f;
    for (int i = tid; i < D; i += 256) s += xr[i];
    sh[tid] = s; __syncthreads();
    for (int o = 128; o; o >>= 1) { if (tid < o) sh[tid] += sh[tid + o]; __syncthreads(); }
    float mu = sh[0] * (1.f / D);
    __syncthreads();

    float v = 0.f;
    for (int i = tid; i < D; i += 256) { float dd = xr[i] - mu; v += dd * dd; }
    sh[tid] = v; __syncthreads();
    for (int o = 128; o; o >>= 1) { if (tid < o) sh[tid] += sh[tid + o]; __syncthreads(); }
    float inv = rsqrtf(sh[0] * (1.f / D) + 1e-6f);

    for (int i = tid; i < D; i += 256)
        out[(size_t)row * D + i] = __float2bfloat16((xr[i] - mu) * inv * g[i] + b[i]);
}

// ---------------- bf16 tensor-core GEMM ----------------
// C[M,N] = A[M,K] @ op(B) (+bias)(relu)(+res). TB==0: B[K,N] row-major; TB==1: B[N,K].
// OB==1: C written as bf16, else fp32. batched over blockIdx.z via strides.
// 64x64 tile, BK=32, 128 threads (4 warps, 2x2 of 32x32 warp tiles).
template<int TB, int OB>
__global__ void wgemm(const bf16* __restrict__ Ag, const bf16* __restrict__ Bg,
                      const float* __restrict__ bias, const float* __restrict__ res,
                      void* __restrict__ Cv, int M, int N, int K, int relu,
                      size_t sA, size_t sB, size_t sBias, size_t sC) {
    const int z = blockIdx.z;
    const bf16* A = Ag + (size_t)z * sA;
    const bf16* B = Bg + (size_t)z * sB;
    const float* bi = bias ? bias + (size_t)z * sBias : nullptr;

    __shared__ __align__(16) char smem_raw[18432];
    bf16*  As = reinterpret_cast<bf16*>(smem_raw);          // [64][40]
    bf16*  Bs = As + 2560;                                  // TB0: [32][72], TB1: [64][40]
    float* Cs = reinterpret_cast<float*>(smem_raw);         // [64][72]

    const int tid  = threadIdx.x;
    const int warp = tid >> 5;
    const int wm   = warp >> 1;   // 0..1
    const int wn   = warp & 1;    // 0..1
    const int m0 = blockIdx.y * 64, n0 = blockIdx.x * 64;

    wmma::fragment<wmma::accumulator, 16, 16, 16, float> acc[2][2];
    #pragma unroll
    for (int i = 0; i < 2; i++)
        #pragma unroll
        for (int j = 0; j < 2; j++) wmma::fill_fragment(acc[i][j], 0.f);

    for (int k0 = 0; k0 < K; k0 += 32) {
        __syncthreads();
        // A tile 64x32
        #pragma unroll
        for (int it = 0; it < 2; it++) {
            int r = (tid >> 2) + it * 32;
            int c = (tid & 3) << 3;
            *reinterpret_cast<uint4*>(&As[r * 40 + c]) =
                *reinterpret_cast<const uint4*>(&A[(size_t)(m0 + r) * K + k0 + c]);
        }
        if (TB == 0) {  // B tile 32x64 from [K,N]
            #pragma unroll
            for (int it = 0; it < 2; it++) {
                int r = (tid >> 3) + it * 16;
                int c = (tid & 7) << 3;
                *reinterpret_cast<uint4*>(&Bs[r * 72 + c]) =
                    *reinterpret_cast<const uint4*>(&B[(size_t)(k0 + r) * N + n0 + c]);
            }
        } else {        // B tile 64x32 from [N,K]
            #pragma unroll
            for (int it = 0; it < 2; it++) {
                int r = (tid >> 2) + it * 32;
                int c = (tid & 3) << 3;
                *reinterpret_cast<uint4*>(&Bs[r * 40 + c]) =
                    *reinterpret_cast<const uint4*>(&B[(size_t)(n0 + r) * K + k0 + c]);
            }
        }
        __syncthreads();

        #pragma unroll
        for (int kk = 0; kk < 32; kk += 16) {
            wmma::fragment<wmma::matrix_a, 16, 16, 16, bf16, wmma::row_major> a0, a1;
            wmma::load_matrix_sync(a0, &As[(wm * 32 +  0) * 40 + kk], 40);
            wmma::load_matrix_sync(a1, &As[(wm * 32 + 16) * 40 + kk], 40);
            if (TB == 0) {
                wmma::fragment<wmma::matrix_b, 16, 16, 16, bf16, wmma::row_major> b0, b1;
                wmma::load_matrix_sync(b0, &Bs[kk * 72 + wn * 32 +  0], 72);
                wmma::load_matrix_sync(b1, &Bs[kk * 72 + wn * 32 + 16], 72);
                wmma::mma_sync(acc[0][0], a0, b0, acc[0][0]);
                wmma::mma_sync(acc[0][1], a0, b1, acc[0][1]);
                wmma::mma_sync(acc[1][0], a1, b0, acc[1][0]);
                wmma::mma_sync(acc[1][1], a1, b1, acc[1][1]);
            } else {
                wmma::fragment<wmma::matrix_b, 16, 16, 16, bf16, wmma::col_major> b0, b1;
                wmma::load_matrix_sync(b0, &Bs[(wn * 32 +  0) * 40 + kk], 40);
                wmma::load_matrix_sync(b1, &Bs[(wn * 32 + 16) * 40 + kk], 40);
                wmma::mma_sync(acc[0][0], a0, b0, acc[0][0]);
                wmma::mma_sync(acc[0][1], a0, b1, acc[0][1]);
                wmma::mma_sync(acc[1][0], a1, b0, acc[1][0]);
                wmma::mma_sync(acc[1][1], a1, b1, acc[1][1]);
            }
        }
    }

    __syncthreads();   // protect As/Bs readers before aliasing Cs
    #pragma unroll
    for (int i = 0; i < 2; i++)
        #pragma unroll
        for (int j = 0; j < 2; j++)
            wmma::store_matrix_sync(&Cs[(wm * 32 + i * 16) * 72 + wn * 32 + j * 16],
                                    acc[i][j], 72, wmma::mem_row_major);
    __syncthreads();

    for (int idx = tid; idx < 64 * 64; idx += 128) {
        int r = idx >> 6, c = idx & 63;
        int m = m0 + r, n = n0 + c;
        float val = Cs[r * 72 + c];
        if (bi)   val += bi[n];
        if (relu) val = fmaxf(val, 0.f);
        if (OB) {
            reinterpret_cast<bf16*>(Cv)[(size_t)z * sC + (size_t)m * N + n] = __float2bfloat16(val);
        } else {
            float* C = reinterpret_cast<float*>(Cv) + (size_t)z * sC;
            if (res) val += res[(size_t)m * N + n];
            C[(size_t)m * N + n] = val;
        }
    }
}

// ---------------- attention scores + softmax (fp32 q,k) ----------------
__global__ void attn_kernel(const float* __restrict__ Q, const float* __restrict__ Kp,
                            const int* __restrict__ toks, int causal,
                            float* __restrict__ scores) {
    int blk = blockIdx.x;
    int q = blk % TT;
    int h = (blk / TT) % H;
    int b = blk / (TT * H);
    int k = threadIdx.x;

    const float* qv = Q + (size_t)(b * TT + q) * D + h * DK;
    const float* kv = Kp + (size_t)(b * TT + k) * D + h * DK;
    float s = 0.f;
    #pragma unroll
    for (int d = 0; d < DK; d++) s += qv[d] * kv[d];
    s *= 0.125f;

    bool masked = (toks[b * TT + k] == 1) || (causal && k > q);
    if (masked) s = -1e30f;

    __shared__ float sh[TT];
    sh[k] = s; __syncthreads();
    for (int o = 64; o; o >>= 1) { if (k < o) sh[k] = fmaxf(sh[k], sh[k + o]); __syncthreads(); }
    float mx = sh[0]; __syncthreads();

    float e = expf(s - mx);
    sh[k] = e; __syncthreads();
    for (int o = 64; o; o >>= 1) { if (k < o) sh[k] += sh[k + o]; __syncthreads(); }
    float sum = sh[0];

    scores[(size_t)blk * TT + k] = e / sum;
}

// ---------------- AV: out bf16 ----------------
__global__ void av_kernel(const float* __restrict__ scores, const float* __restrict__ Vp,
                          bf16* __restrict__ out) {
    int row = blockIdx.x;
    int b = row / TT, q = row % TT;
    int t = threadIdx.x;
    int h = t / DK;
    const float* a = scores + (size_t)((b * H + h) * TT + q) * TT;
    float acc = 0.f;
    #pragma unroll 4
    for (int k = 0; k < TT; k++)
        acc += a[k] * Vp[(size_t)(b * TT + k) * D + t];
    out[(size_t)row * D + t] = __float2bfloat16(acc);
}

// ---------------- log_softmax in place ----------------
__global__ void logsoftmax_kernel(float* __restrict__ logits) {
    int row = blockIdx.x;
    float* x = logits + (size_t)row * VV;
    __shared__ float sh[256];
    int tid = threadIdx.x;

    float mx = -1e30f;
    for (int i = tid; i < VV; i += 256) mx = fmaxf(mx, x[i]);
    sh[tid] = mx; __syncthreads();
    for (int o = 128; o; o >>= 1) { if (tid < o) sh[tid] = fmaxf(sh[tid], sh[tid + o]); __syncthreads(); }
    float M = sh[0]; __syncthreads();

    float s = 0.f;
    for (int i = tid; i < VV; i += 256) s += expf(x[i] - M);
    sh[tid] = s; __syncthreads();
    for (int o = 128; o; o >>= 1) { if (tid < o) sh[tid] += sh[tid + o]; __syncthreads(); }
    float lse = M + logf(sh[0]);

    for (int i = tid; i < VV; i += 256) x[i] -= lse;
}

// ---------------- host helpers ----------------
static void G(const bf16* A, const bf16* B, const float* bias, const float* res,
              void* C, int M, int N, int K, int relu, int tb, int ob, int batch,
              size_t sA, size_t sB, size_t sBias, size_t sC) {
    dim3 grid(N / 64, M / 64, batch);
    if (tb)      wgemm<1, 0><<<grid, 128>>>(A, B, bias, res, C, M, N, K, relu, sA, sB, sBias, sC);
    else if (ob) wgemm<0, 1><<<grid, 128>>>(A, B, bias, res, C, M, N, K, relu, sA, sB, sBias, sC);
    else         wgemm<0, 0><<<grid, 128>>>(A, B, bias, res, C, M, N, K, relu, sA, sB, sBias, sC);
}

static void CVT(const float* s, bf16* d, size_t n) {
    int n4 = (int)(n / 4);
    f2b_kernel<<<(n4 + 255) / 256, 256>>>(s, d, n4);
}

extern "C" void kernel_launch(void* const* d_in, const int* in_sizes, int n_in,
                              void* d_out, int out_size) {
    const int*   src        = (const int*)  d_in[0];
    const int*   tgt        = (const int*)  d_in[1];
    const float* tok_emb    = (const float*)d_in[2];
    const float* pos_emb    = (const float*)d_in[3];
    const float* enc_attn_w = (const float*)d_in[4];
    const float* enc_attn_b = (const float*)d_in[5];
    const float* enc_ffn_w1 = (const float*)d_in[6];
    const float* enc_ffn_b1 = (const float*)d_in[7];
    const float* enc_ffn_w2 = (const float*)d_in[8];
    const float* enc_ffn_b2 = (const float*)d_in[9];
    const float* enc_ln     = (const float*)d_in[10];
    const float* enc_fln    = (const float*)d_in[11];
    const float* dec_attn_w = (const float*)d_in[12];
    const float* dec_attn_b = (const float*)d_in[13];
    const float* dec_ffn_w1 = (const float*)d_in[14];
    const float* dec_ffn_b1 = (const float*)d_in[15];
    const float* dec_ffn_w2 = (const float*)d_in[16];
    const float* dec_ffn_b2 = (const float*)d_in[17];
    const float* dec_ln     = (const float*)d_in[18];
    const float* dec_fln    = (const float*)d_in[19];
    float* out = (float*)d_out;

    float *x, *qkv, *sc;
    bf16 *hb, *aob, *memb, *ffnb, *wp;
    cudaGetSymbolAddress((void**)&x,    g_x);
    cudaGetSymbolAddress((void**)&qkv,  g_qkv);
    cudaGetSymbolAddress((void**)&sc,   g_sc);
    cudaGetSymbolAddress((void**)&hb,   g_hb);
    cudaGetSymbolAddress((void**)&aob,  g_aob);
    cudaGetSymbolAddress((void**)&memb, g_memb);
    cudaGetSymbolAddress((void**)&ffnb, g_ffnb);
    cudaGetSymbolAddress((void**)&wp,   g_wpool);

    const size_t DD = (size_t)D * D;

    // weight conversions (fp32 -> bf16 pool)
    CVT(enc_attn_w, wp + OFF_EA,  N_EA);
    CVT(enc_ffn_w1, wp + OFF_EF1, N_EF1);
    CVT(enc_ffn_w2, wp + OFF_EF2, N_EF2);
    CVT(dec_attn_w, wp + OFF_DA,  N_DA);
    CVT(dec_ffn_w1, wp + OFF_DF1, N_DF1);
    CVT(dec_ffn_w2, wp + OFF_DF2, N_DF2);
    CVT(tok_emb,    wp + OFF_EMB, N_EMB);

    // ================= encoder =================
    embed_kernel<<<(MROWS * D + 255) / 256, 256>>>(src, tok_emb, pos_emb, x);
    for (int i = 0; i < NL; i++) {
        const bf16*  W   = wp + OFF_EA + (size_t)i * 4 * DD;
        const float* Wb  = enc_attn_b + (size_t)i * 4 * D;
        const float* lnp = enc_ln + (size_t)i * 4 * D;

        ln_kernel<<<MROWS, 256>>>(x, lnp, lnp + D, hb);
        G(hb, W, Wb, nullptr, qkv, MROWS, D, D, 0, 0, 0, 3, 0, DD, D, MD);  // q,k,v batched
        attn_kernel<<<BBATCH * H * TT, TT>>>(qkv, qkv + MD, src, 0, sc);
        av_kernel<<<MROWS, D>>>(sc, qkv + 2 * MD, aob);
        G(aob, W + 3 * DD, Wb + 3 * D, x, x, MROWS, D, D, 0, 0, 0, 1, 0, 0, 0, 0);

        ln_kernel<<<MROWS, 256>>>(x, lnp + 2 * D, lnp + 3 * D, hb);
        G(hb, wp + OFF_EF1 + (size_t)i * D * FF, enc_ffn_b1 + (size_t)i * FF,
          nullptr, ffnb, MROWS, FF, D, 1, 0, 1, 1, 0, 0, 0, 0);
        G(ffnb, wp + OFF_EF2 + (size_t)i * FF * D, enc_ffn_b2 + (size_t)i * D,
          x, x, MROWS, D, FF, 0, 0, 0, 1, 0, 0, 0, 0);
    }
    ln_kernel<<<MROWS, 256>>>(x, enc_fln, enc_fln + D, memb);

    // ================= decoder =================
    embed_kernel<<<(MROWS * D + 255) / 256, 256>>>(tgt, tok_emb, pos_emb, x);
    for (int i = 0; i < NL; i++) {
        const bf16*  W   = wp + OFF_DA + (size_t)i * 8 * DD;
        const float* Wb  = dec_attn_b + (size_t)i * 8 * D;
        const float* lnp = dec_ln + (size_t)i * 6 * D;

        // self-attention (causal + tgt pad)
        ln_kernel<<<MROWS, 256>>>(x, lnp, lnp + D, hb);
        G(hb, W, Wb, nullptr, qkv, MROWS, D, D, 0, 0, 0, 3, 0, DD, D, MD);
        attn_kernel<<<BBATCH * H * TT, TT>>>(qkv, qkv + MD, tgt, 1, sc);
        av_kernel<<<MROWS, D>>>(sc, qkv + 2 * MD, aob);
        G(aob, W + 3 * DD, Wb + 3 * D, x, x, MROWS, D, D, 0, 0, 0, 1, 0, 0, 0, 0);

        // cross-attention
        ln_kernel<<<MROWS, 256>>>(x, lnp + 2 * D, lnp + 3 * D, hb);
        G(hb,   W + 4 * DD, Wb + 4 * D, nullptr, qkv, MROWS, D, D, 0, 0, 0, 1, 0, 0, 0, 0);
        G(memb, W + 5 * DD, Wb + 5 * D, nullptr, qkv + MD, MROWS, D, D, 0, 0, 0, 2, 0, DD, D, MD);
        attn_kernel<<<BBATCH * H * TT, TT>>>(qkv, qkv + MD, src, 0, sc);
        av_kernel<<<MROWS, D>>>(sc, qkv + 2 * MD, aob);
        G(aob, W + 7 * DD, Wb + 7 * D, x, x, MROWS, D, D, 0, 0, 0, 1, 0, 0, 0, 0);

        // FFN
        ln_kernel<<<MROWS, 256>>>(x, lnp + 4 * D, lnp + 5 * D, hb);
        G(hb, wp + OFF_DF1 + (size_t)i * D * FF, dec_ffn_b1 + (size_t)i * FF,
          nullptr, ffnb, MROWS, FF, D, 1, 0, 1, 1, 0, 0, 0, 0);
        G(ffnb, wp + OFF_DF2 + (size_t)i * FF * D, dec_ffn_b2 + (size_t)i * D,
          x, x, MROWS, D, FF, 0, 0, 0, 1, 0, 0, 0, 0);
    }
    ln_kernel<<<MROWS, 256>>>(x, dec_fln, dec_fln + D, hb);

    // ============ generator: tied projection + log_softmax ============
    G(hb, wp + OFF_EMB, nullptr, nullptr, out, MROWS, VV, D, 0, 1, 0, 1, 0, 0, 0, 0);
    logsoftmax_kernel<<<MROWS, 256>>>(out);
}

// round 3
// speedup vs baseline: 2.4298x; 1.5066x over previous
#include <cuda_runtime.h>
#include <cuda_bf16.h>
#include <mma.h>
#include <cstddef>

using namespace nvcuda;
typedef __nv_bfloat16 bf16;

// ---------------- problem constants ----------------
#define D    512
#define H    8
#define DK   64
#define TT   128
#define BBATCH 8
#define NL   6
#define VV   32000
#define FF   2048
#define MROWS (BBATCH*TT)   // 1024
#define MD   (MROWS*D)

// weight bf16 pool offsets
#define N_EA  (NL*4*D*D)
#define N_EF1 (NL*D*FF)
#define N_EF2 (NL*FF*D)
#define N_DA  (NL*8*D*D)
#define N_DF1 (NL*D*FF)
#define N_DF2 (NL*FF*D)
#define N_EMB (VV*D)
#define OFF_EA   0
#define OFF_EF1  (OFF_EA + N_EA)
#define OFF_EF2  (OFF_EF1 + N_EF1)
#define OFF_DA   (OFF_EF2 + N_EF2)
#define OFF_DF1  (OFF_DA + N_DA)
#define OFF_DF2  (OFF_DF1 + N_DF1)
#define OFF_EMB  (OFF_DF2 + N_DF2)
#define WPOOL_N  (OFF_EMB + N_EMB)

// ---------------- scratch ----------------
__device__ float g_x  [MD];
__device__ bf16  g_qkv[3*MD];
__device__ float g_sc [BBATCH*H*TT*TT];
__device__ bf16  g_hb [MD];
__device__ bf16  g_aob[MD];
__device__ bf16  g_memb[MD];
__device__ bf16  g_ffnb[MROWS*FF];
__device__ bf16  g_wpool[WPOOL_N];

// ---------------- cp.async helpers ----------------
__device__ __forceinline__ void cpa16(void* dst, const void* src) {
    unsigned sdst = (unsigned)__cvta_generic_to_shared(dst);
    asm volatile("cp.async.cg.shared.global [%0], [%1], 16;\n" :: "r"(sdst), "l"(src));
}
__device__ __forceinline__ void cpa_commit() {
    asm volatile("cp.async.commit_group;\n");
}
template<int N>
__device__ __forceinline__ void cpa_wait() {
    asm volatile("cp.async.wait_group %0;\n" :: "n"(N));
}

// ---------------- fp32 -> bf16 conversion ----------------
__global__ void f2b_kernel(const float* __restrict__ s, bf16* __restrict__ d, int n4) {
    int i = blockIdx.x * blockDim.x + threadIdx.x;
    if (i >= n4) return;
    float4 v = reinterpret_cast<const float4*>(s)[i];
    __nv_bfloat162* o = reinterpret_cast<__nv_bfloat162*>(d) + 2 * i;
    o[0] = __floats2bfloat162_rn(v.x, v.y);
    o[1] = __floats2bfloat162_rn(v.z, v.w);
}

// ---------------- embedding ----------------
__global__ void embed_kernel(const int* __restrict__ tok,
                             const float* __restrict__ tok_emb,
                             const float* __restrict__ pos_emb,
                             float* __restrict__ out) {
    int idx = blockIdx.x * blockDim.x + threadIdx.x;
    if (idx >= MROWS * D) return;
    int row = idx / D, d = idx % D;
    int t = row % TT;
    out[idx] = tok_emb[(size_t)tok[row] * D + d] + pos_emb[(size_t)t * D + d];
}

// ---------------- layernorm -> bf16 ----------------
__global__ void ln_kernel(const float* __restrict__ x,
                          const float* __restrict__ g,
                          const float* __restrict__ b,
                          bf16* __restrict__ out) {
    int row = blockIdx.x;
    const float* xr = x + (size_t)row * D;
    __shared__ float sh[256];
    int tid = threadIdx.x;

    float s = 0.f;
    for (int i = tid; i < D; i += 256) s += xr[i];
    sh[tid] = s; __syncthreads();
    for (int o = 128; o; o >>= 1) { if (tid < o) sh[tid] += sh[tid + o]; __syncthreads(); }
    float mu = sh[0] * (1.f / D);
    __syncthreads();

    float v = 0.f;
    for (int i = tid; i < D; i += 256) { float dd = xr[i] - mu; v += dd * dd; }
    sh[tid] = v; __syncthreads();
    for (int o = 128; o; o >>= 1) { if (tid < o) sh[tid] += sh[tid + o]; __syncthreads(); }
    float inv = rsqrtf(sh[0] * (1.f / D) + 1e-6f);

    for (int i = tid; i < D; i += 256)
        out[(size_t)row * D + i] = __float2bfloat16((xr[i] - mu) * inv * g[i] + b[i]);
}

// ---------------- bf16 tensor-core GEMM, cp.async double-buffered ----------------
// 128x64 block tile, BK=32, 256 threads = 8 warps (4 along M x 2 along N), warp=32x32.
// TB==0: B[K,N]; TB==1: B[N,K]. OB==1 -> bf16 out, else fp32 (+optional fp32 residual).
#define ASTR 48
#define BSTR0 72
#define BSTR1 48
#define ASZ (128*ASTR)       // elems per stage
#define BSZ (64*BSTR1)       // max of the two B stage sizes (3072)

template<int TB, int OB>
__global__ __launch_bounds__(256) void wgemm(
        const bf16* __restrict__ Ag, const bf16* __restrict__ Bg,
        const float* __restrict__ bias, const float* __restrict__ res,
        void* __restrict__ Cv, int M, int N, int K, int relu,
        size_t sA, size_t sB, size_t sBias, size_t sC) {
    const int z = blockIdx.z;
    const bf16* A = Ag + (size_t)z * sA;
    const bf16* B = Bg + (size_t)z * sB;
    const float* bi = bias ? bias + (size_t)z * sBias : nullptr;

    __shared__ __align__(16) char smem_raw[36864];
    bf16*  Abase = reinterpret_cast<bf16*>(smem_raw);
    bf16*  Bbase = Abase + 2 * ASZ;
    float* Cs    = reinterpret_cast<float*>(smem_raw);   // 128 x 72 fp32 (epilogue)

    const int tid  = threadIdx.x;
    const int warp = tid >> 5;
    const int wm   = warp & 3;       // 0..3 (M)
    const int wn   = warp >> 2;      // 0..1 (N)
    const int m0 = blockIdx.y * 128, n0 = blockIdx.x * 64;

    wmma::fragment<wmma::accumulator, 16, 16, 16, float> acc[2][2];
    #pragma unroll
    for (int i = 0; i < 2; i++)
        #pragma unroll
        for (int j = 0; j < 2; j++) wmma::fill_fragment(acc[i][j], 0.f);

    auto load_stage = [&](int s, int k0) {
        bf16* As = Abase + s * ASZ;
        bf16* Bs = Bbase + s * BSZ;
        #pragma unroll
        for (int it = 0; it < 2; it++) {            // A: 128x32, 512 16B-chunks
            int chunk = tid + it * 256;
            int r = chunk >> 2, c = (chunk & 3) << 3;
            cpa16(&As[r * ASTR + c], &A[(size_t)(m0 + r) * K + k0 + c]);
        }
        if (TB == 0) {                              // B: 32x64 from [K,N]
            int r = tid >> 3, c = (tid & 7) << 3;
            cpa16(&Bs[r * BSTR0 + c], &B[(size_t)(k0 + r) * N + n0 + c]);
        } else {                                    // B: 64x32 from [N,K]
            int r = tid >> 2, c = (tid & 3) << 3;
            cpa16(&Bs[r * BSTR1 + c], &B[(size_t)(n0 + r) * K + k0 + c]);
        }
    };

    auto compute_stage = [&](int s) {
        bf16* As = Abase + s * ASZ;
        bf16* Bs = Bbase + s * BSZ;
        #pragma unroll
        for (int kk = 0; kk < 32; kk += 16) {
            wmma::fragment<wmma::matrix_a, 16, 16, 16, bf16, wmma::row_major> a0, a1;
            wmma::load_matrix_sync(a0, &As[(wm * 32 +  0) * ASTR + kk], ASTR);
            wmma::load_matrix_sync(a1, &As[(wm * 32 + 16) * ASTR + kk], ASTR);
            if (TB == 0) {
                wmma::fragment<wmma::matrix_b, 16, 16, 16, bf16, wmma::row_major> b0, b1;
                wmma::load_matrix_sync(b0, &Bs[kk * BSTR0 + wn * 32 +  0], BSTR0);
                wmma::load_matrix_sync(b1, &Bs[kk * BSTR0 + wn * 32 + 16], BSTR0);
                wmma::mma_sync(acc[0][0], a0, b0, acc[0][0]);
                wmma::mma_sync(acc[0][1], a0, b1, acc[0][1]);
                wmma::mma_sync(acc[1][0], a1, b0, acc[1][0]);
                wmma::mma_sync(acc[1][1], a1, b1, acc[1][1]);
            } else {
                wmma::fragment<wmma::matrix_b, 16, 16, 16, bf16, wmma::col_major> b0, b1;
                wmma::load_matrix_sync(b0, &Bs[(wn * 32 +  0) * BSTR1 + kk], BSTR1);
                wmma::load_matrix_sync(b1, &Bs[(wn * 32 + 16) * BSTR1 + kk], BSTR1);
                wmma::mma_sync(acc[0][0], a0, b0, acc[0][0]);
                wmma::mma_sync(acc[0][1], a0, b1, acc[0][1]);
                wmma::mma_sync(acc[1][0], a1, b0, acc[1][0]);
                wmma::mma_sync(acc[1][1], a1, b1, acc[1][1]);
            }
        }
    };

    const int KT = K >> 5;
    load_stage(0, 0);
    cpa_commit();
    for (int kt = 0; kt < KT; kt++) {
        if (kt + 1 < KT) { load_stage((kt + 1) & 1, (kt + 1) << 5); cpa_commit(); cpa_wait<1>(); }
        else             { cpa_wait<0>(); }
        __syncthreads();
        compute_stage(kt & 1);
        __syncthreads();
    }

    // epilogue: stage accumulators to smem (aliases tiles; loop ended with sync)
    #pragma unroll
    for (int i = 0; i < 2; i++)
        #pragma unroll
        for (int j = 0; j < 2; j++)
            wmma::store_matrix_sync(&Cs[(wm * 32 + i * 16) * 72 + wn * 32 + j * 16],
                                    acc[i][j], 72, wmma::mem_row_major);
    __syncthreads();

    #pragma unroll
    for (int it = 0; it < 32; it++) {
        int idx = tid + it * 256;
        int r = idx >> 6, c = idx & 63;
        int m = m0 + r, n = n0 + c;
        float val = Cs[r * 72 + c];
        if (bi)   val += bi[n];
        if (relu) val = fmaxf(val, 0.f);
        if (OB) {
            reinterpret_cast<bf16*>(Cv)[(size_t)z * sC + (size_t)m * N + n] = __float2bfloat16(val);
        } else {
            float* C = reinterpret_cast<float*>(Cv) + (size_t)z * sC;
            if (res) val += res[(size_t)m * N + n];
            C[(size_t)m * N + n] = val;
        }
    }
}

// ---------------- attention scores + softmax (bf16 q,k) ----------------
__global__ void attn_kernel(const bf16* __restrict__ Q, const bf16* __restrict__ Kp,
                            const int* __restrict__ toks, int causal,
                            float* __restrict__ scores) {
    int blk = blockIdx.x;
    int q = blk % TT;
    int h = (blk / TT) % H;
    int b = blk / (TT * H);
    int k = threadIdx.x;

    const __nv_bfloat162* qv = reinterpret_cast<const __nv_bfloat162*>(
        Q + (size_t)(b * TT + q) * D + h * DK);
    const __nv_bfloat162* kv = reinterpret_cast<const __nv_bfloat162*>(
        Kp + (size_t)(b * TT + k) * D + h * DK);
    float s = 0.f;
    #pragma unroll
    for (int d = 0; d < DK / 2; d++) {
        float2 qq = __bfloat1622float2(qv[d]);
        float2 kk = __bfloat1622float2(kv[d]);
        s += qq.x * kk.x + qq.y * kk.y;
    }
    s *= 0.125f;

    bool masked = (toks[b * TT + k] == 1) || (causal && k > q);
    if (masked) s = -1e30f;

    __shared__ float sh[TT];
    sh[k] = s; __syncthreads();
    for (int o = 64; o; o >>= 1) { if (k < o) sh[k] = fmaxf(sh[k], sh[k + o]); __syncthreads(); }
    float mx = sh[0]; __syncthreads();

    float e = expf(s - mx);
    sh[k] = e; __syncthreads();
    for (int o = 64; o; o >>= 1) { if (k < o) sh[k] += sh[k + o]; __syncthreads(); }
    float sum = sh[0];

    scores[(size_t)blk * TT + k] = e / sum;
}

// ---------------- AV: bf16 V -> bf16 out ----------------
__global__ void av_kernel(const float* __restrict__ scores, const bf16* __restrict__ Vp,
                          bf16* __restrict__ out) {
    int row = blockIdx.x;
    int b = row / TT, q = row % TT;
    int t = threadIdx.x;
    int h = t / DK;
    const float* a = scores + (size_t)((b * H + h) * TT + q) * TT;
    float acc = 0.f;
    #pragma unroll 4
    for (int k = 0; k < TT; k++)
        acc += a[k] * __bfloat162float(Vp[(size_t)(b * TT + k) * D + t]);
    out[(size_t)row * D + t] = __float2bfloat16(acc);
}

// ---------------- log_softmax in place ----------------
__global__ void logsoftmax_kernel(float* __restrict__ logits) {
    int row = blockIdx.x;
    float* x = logits + (size_t)row * VV;
    __shared__ float sh[256];
    int tid = threadIdx.x;

    float mx = -1e30f;
    for (int i = tid; i < VV; i += 256) mx = fmaxf(mx, x[i]);
    sh[tid] = mx; __syncthreads();
    for (int o = 128; o; o >>= 1) { if (tid < o) sh[tid] = fmaxf(sh[tid], sh[tid + o]); __syncthreads(); }
    float M = sh[0]; __syncthreads();

    float s = 0.f;
    for (int i = tid; i < VV; i += 256) s += expf(x[i] - M);
    sh[tid] = s; __syncthreads();
    for (int o = 128; o; o >>= 1) { if (tid < o) sh[tid] += sh[tid + o]; __syncthreads(); }
    float lse = M + logf(sh[0]);

    for (int i = tid; i < VV; i += 256) x[i] -= lse;
}

// ---------------- host helpers ----------------
static void G(const bf16* A, const bf16* B, const float* bias, const float* res,
              void* C, int M, int N, int K, int relu, int tb, int ob, int batch,
              size_t sA, size_t sB, size_t sBias, size_t sC) {
    dim3 grid(N / 64, M / 128, batch);
    if (tb)      wgemm<1, 0><<<grid, 256>>>(A, B, bias, res, C, M, N, K, relu, sA, sB, sBias, sC);
    else if (ob) wgemm<0, 1><<<grid, 256>>>(A, B, bias, res, C, M, N, K, relu, sA, sB, sBias, sC);
    else         wgemm<0, 0><<<grid, 256>>>(A, B, bias, res, C, M, N, K, relu, sA, sB, sBias, sC);
}

static void CVT(const float* s, bf16* d, size_t n) {
    int n4 = (int)(n / 4);
    f2b_kernel<<<(n4 + 255) / 256, 256>>>(s, d, n4);
}

extern "C" void kernel_launch(void* const* d_in, const int* in_sizes, int n_in,
                              void* d_out, int out_size) {
    const int*   src        = (const int*)  d_in[0];
    const int*   tgt        = (const int*)  d_in[1];
    const float* tok_emb    = (const float*)d_in[2];
    const float* pos_emb    = (const float*)d_in[3];
    const float* enc_attn_w = (const float*)d_in[4];
    const float* enc_attn_b = (const float*)d_in[5];
    const float* enc_ffn_w1 = (const float*)d_in[6];
    const float* enc_ffn_b1 = (const float*)d_in[7];
    const float* enc_ffn_w2 = (const float*)d_in[8];
    const float* enc_ffn_b2 = (const float*)d_in[9];
    const float* enc_ln     = (const float*)d_in[10];
    const float* enc_fln    = (const float*)d_in[11];
    const float* dec_attn_w = (const float*)d_in[12];
    const float* dec_attn_b = (const float*)d_in[13];
    const float* dec_ffn_w1 = (const float*)d_in[14];
    const float* dec_ffn_b1 = (const float*)d_in[15];
    const float* dec_ffn_w2 = (const float*)d_in[16];
    const float* dec_ffn_b2 = (const float*)d_in[17];
    const float* dec_ln     = (const float*)d_in[18];
    const float* dec_fln    = (const float*)d_in[19];
    float* out = (float*)d_out;

    float *x, *sc;
    bf16 *qkv, *hb, *aob, *memb, *ffnb, *wp;
    cudaGetSymbolAddress((void**)&x,    g_x);
    cudaGetSymbolAddress((void**)&qkv,  g_qkv);
    cudaGetSymbolAddress((void**)&sc,   g_sc);
    cudaGetSymbolAddress((void**)&hb,   g_hb);
    cudaGetSymbolAddress((void**)&aob,  g_aob);
    cudaGetSymbolAddress((void**)&memb, g_memb);
    cudaGetSymbolAddress((void**)&ffnb, g_ffnb);
    cudaGetSymbolAddress((void**)&wp,   g_wpool);

    const size_t DD = (size_t)D * D;

    CVT(enc_attn_w, wp + OFF_EA,  N_EA);
    CVT(enc_ffn_w1, wp + OFF_EF1, N_EF1);
    CVT(enc_ffn_w2, wp + OFF_EF2, N_EF2);
    CVT(dec_attn_w, wp + OFF_DA,  N_DA);
    CVT(dec_ffn_w1, wp + OFF_DF1, N_DF1);
    CVT(dec_ffn_w2, wp + OFF_DF2, N_DF2);
    CVT(tok_emb,    wp + OFF_EMB, N_EMB);

    // ================= encoder =================
    embed_kernel<<<(MROWS * D + 255) / 256, 256>>>(src, tok_emb, pos_emb, x);
    for (int i = 0; i < NL; i++) {
        const bf16*  W   = wp + OFF_EA + (size_t)i * 4 * DD;
        const float* Wb  = enc_attn_b + (size_t)i * 4 * D;
        const float* lnp = enc_ln + (size_t)i * 4 * D;

        ln_kernel<<<MROWS, 256>>>(x, lnp, lnp + D, hb);
        G(hb, W, Wb, nullptr, qkv, MROWS, D, D, 0, 0, 1, 3, 0, DD, D, MD);
        attn_kernel<<<BBATCH * H * TT, TT>>>(qkv, qkv + MD, src, 0, sc);
        av_kernel<<<MROWS, D>>>(sc, qkv + 2 * MD, aob);
        G(aob, W + 3 * DD, Wb + 3 * D, x, x, MROWS, D, D, 0, 0, 0, 1, 0, 0, 0, 0);

        ln_kernel<<<MROWS, 256>>>(x, lnp + 2 * D, lnp + 3 * D, hb);
        G(hb, wp + OFF_EF1 + (size_t)i * D * FF, enc_ffn_b1 + (size_t)i * FF,
          nullptr, ffnb, MROWS, FF, D, 1, 0, 1, 1, 0, 0, 0, 0);
        G(ffnb, wp + OFF_EF2 + (size_t)i * FF * D, enc_ffn_b2 + (size_t)i * D,
          x, x, MROWS, D, FF, 0, 0, 0, 1, 0, 0, 0, 0);
    }
    ln_kernel<<<MROWS, 256>>>(x, enc_fln, enc_fln + D, memb);

    // ================= decoder =================
    embed_kernel<<<(MROWS * D + 255) / 256, 256>>>(tgt, tok_emb, pos_emb, x);
    for (int i = 0; i < NL; i++) {
        const bf16*  W   = wp + OFF_DA + (size_t)i * 8 * DD;
        const float* Wb  = dec_attn_b + (size_t)i * 8 * D;
        const float* lnp = dec_ln + (size_t)i * 6 * D;

        // self-attention (causal + tgt pad)
        ln_kernel<<<MROWS, 256>>>(x, lnp, lnp + D, hb);
        G(hb, W, Wb, nullptr, qkv, MROWS, D, D, 0, 0, 1, 3, 0, DD, D, MD);
        attn_kernel<<<BBATCH * H * TT, TT>>>(qkv, qkv + MD, tgt, 1, sc);
        av_kernel<<<MROWS, D>>>(sc, qkv + 2 * MD, aob);
        G(aob, W + 3 * DD, Wb + 3 * D, x, x, MROWS, D, D, 0, 0, 0, 1, 0, 0, 0, 0);

        // cross-attention
        ln_kernel<<<MROWS, 256>>>(x, lnp + 2 * D, lnp + 3 * D, hb);
        G(hb,   W + 4 * DD, Wb + 4 * D, nullptr, qkv, MROWS, D, D, 0, 0, 1, 1, 0, 0, 0, MD);
        G(memb, W + 5 * DD, Wb + 5 * D, nullptr, qkv + MD, MROWS, D, D, 0, 0, 1, 2, 0, DD, D, MD);
        attn_kernel<<<BBATCH * H * TT, TT>>>(qkv, qkv + MD, src, 0, sc);
        av_kernel<<<MROWS, D>>>(sc, qkv + 2 * MD, aob);
        G(aob, W + 7 * DD, Wb + 7 * D, x, x, MROWS, D, D, 0, 0, 0, 1, 0, 0, 0, 0);

        // FFN
        ln_kernel<<<MROWS, 256>>>(x, lnp + 4 * D, lnp + 5 * D, hb);
        G(hb, wp + OFF_DF1 + (size_t)i * D * FF, dec_ffn_b1 + (size_t)i * FF,
          nullptr, ffnb, MROWS, FF, D, 1, 0, 1, 1, 0, 0, 0, 0);
        G(ffnb, wp + OFF_DF2 + (size_t)i * FF * D, dec_ffn_b2 + (size_t)i * D,
          x, x, MROWS, D, FF, 0, 0, 0, 1, 0, 0, 0, 0);
    }
    ln_kernel<<<MROWS, 256>>>(x, dec_fln, dec_fln + D, hb);

    // ============ generator: tied projection + log_softmax ============
    G(hb, wp + OFF_EMB, nullptr, nullptr, out, MROWS, VV, D, 0, 1, 0, 1, 0, 0, 0, 0);
    logsoftmax_kernel<<<MROWS, 256>>>(out);
}

// round 4
// speedup vs baseline: 6.7676x; 2.7852x over previous
#include <cuda_runtime.h>
#include <cuda_bf16.h>
#include <mma.h>
#include <cstddef>

using namespace nvcuda;
typedef __nv_bfloat16 bf16;

#define D    512
#define H    8
#define DK   64
#define TT   128
#define BBATCH 8
#define NL   6
#define VV   32000
#define FF   2048
#define MROWS (BBATCH*TT)
#define MD   (MROWS*D)

#define N_EA  (NL*4*D*D)
#define N_EF1 (NL*D*FF)
#define N_EF2 (NL*FF*D)
#define N_DA  (NL*8*D*D)
#define N_DF1 (NL*D*FF)
#define N_DF2 (NL*FF*D)
#define N_EMB (VV*D)
#define OFF_EA   0
#define OFF_EF1  (OFF_EA + N_EA)
#define OFF_EF2  (OFF_EF1 + N_EF1)
#define OFF_DA   (OFF_EF2 + N_EF2)
#define OFF_DF1  (OFF_DA + N_DA)
#define OFF_DF2  (OFF_DF1 + N_DF1)
#define OFF_EMB  (OFF_DF2 + N_DF2)
#define WPOOL_N  (OFF_EMB + N_EMB)

__device__ float g_x  [MD];
__device__ bf16  g_qkv[3*MD];
__device__ bf16  g_hb [MD];
__device__ bf16  g_aob[MD];
__device__ bf16  g_memb[MD];
__device__ bf16  g_ffnb[MROWS*FF];
__device__ bf16  g_kc [NL*MD];
__device__ bf16  g_vc [NL*MD];
__device__ bf16  g_wpool[WPOOL_N];

// ---------------- cp.async helpers ----------------
__device__ __forceinline__ void cpa16(void* dst, const void* src) {
    unsigned sdst = (unsigned)__cvta_generic_to_shared(dst);
    asm volatile("cp.async.cg.shared.global [%0], [%1], 16;\n" :: "r"(sdst), "l"(src));
}
__device__ __forceinline__ void cpa_commit() { asm volatile("cp.async.commit_group;\n"); }
template<int N>
__device__ __forceinline__ void cpa_wait() { asm volatile("cp.async.wait_group %0;\n" :: "n"(N)); }

// ---------------- fp32 -> bf16 ----------------
__global__ void f2b_kernel(const float* __restrict__ s, bf16* __restrict__ d, int n4) {
    int i = blockIdx.x * blockDim.x + threadIdx.x;
    if (i >= n4) return;
    float4 v = reinterpret_cast<const float4*>(s)[i];
    __nv_bfloat162* o = reinterpret_cast<__nv_bfloat162*>(d) + 2 * i;
    o[0] = __floats2bfloat162_rn(v.x, v.y);
    o[1] = __floats2bfloat162_rn(v.z, v.w);
}

// ---------------- embedding ----------------
__global__ void embed_kernel(const int* __restrict__ tok,
                             const float* __restrict__ tok_emb,
                             const float* __restrict__ pos_emb,
                             float* __restrict__ out) {
    int idx = blockIdx.x * blockDim.x + threadIdx.x;
    if (idx >= MROWS * D) return;
    int row = idx / D, d = idx % D;
    int t = row % TT;
    out[idx] = tok_emb[(size_t)tok[row] * D + d] + pos_emb[(size_t)t * D + d];
}

// ---------------- layernorm: warp per row, 8 rows/block ----------------
__global__ __launch_bounds__(256) void ln_kernel(const float* __restrict__ x,
                          const float* __restrict__ g,
                          const float* __restrict__ b,
                          bf16* __restrict__ out) {
    int row  = blockIdx.x * 8 + (threadIdx.x >> 5);
    int lane = threadIdx.x & 31;
    const float4* xr = reinterpret_cast<const float4*>(x + (size_t)row * D);

    float4 v[4];
    float s = 0.f;
    #pragma unroll
    for (int j = 0; j < 4; j++) {
        v[j] = xr[lane + j * 32];
        s += v[j].x + v[j].y + v[j].z + v[j].w;
    }
    #pragma unroll
    for (int o = 16; o; o >>= 1) s += __shfl_xor_sync(0xffffffffu, s, o);
    float mu = s * (1.f / D);

    float var = 0.f;
    #pragma unroll
    for (int j = 0; j < 4; j++) {
        float a0 = v[j].x - mu, a1 = v[j].y - mu, a2 = v[j].z - mu, a3 = v[j].w - mu;
        var += a0 * a0 + a1 * a1 + a2 * a2 + a3 * a3;
    }
    #pragma unroll
    for (int o = 16; o; o >>= 1) var += __shfl_xor_sync(0xffffffffu, var, o);
    float inv = rsqrtf(var * (1.f / D) + 1e-6f);

    const float4* g4 = reinterpret_cast<const float4*>(g);
    const float4* b4 = reinterpret_cast<const float4*>(b);
    uint2* o8 = reinterpret_cast<uint2*>(out + (size_t)row * D);
    #pragma unroll
    for (int j = 0; j < 4; j++) {
        int c = lane + j * 32;
        float4 gg = g4[c], bb = b4[c];
        float r0 = (v[j].x - mu) * inv * gg.x + bb.x;
        float r1 = (v[j].y - mu) * inv * gg.y + bb.y;
        float r2 = (v[j].z - mu) * inv * gg.z + bb.z;
        float r3 = (v[j].w - mu) * inv * gg.w + bb.w;
        __nv_bfloat162 lo = __floats2bfloat162_rn(r0, r1);
        __nv_bfloat162 hi = __floats2bfloat162_rn(r2, r3);
        uint2 pk; pk.x = *reinterpret_cast<unsigned*>(&lo); pk.y = *reinterpret_cast<unsigned*>(&hi);
        o8[c] = pk;
    }
}

// ---------------- bf16 tensor-core GEMM, cp.async double-buffered ----------------
#define ASTR 48
#define BSTR0 72
#define BSTR1 48
#define BSZ (64*BSTR1)

template<int TB, int OB, int MT>
__global__ __launch_bounds__(256) void wgemm(
        const bf16* __restrict__ Ag, const bf16* __restrict__ Bg,
        const float* __restrict__ bias, const float* __restrict__ res,
        void* __restrict__ Cv, int M, int N, int K, int relu,
        size_t sA, size_t sB, size_t sBias, size_t sC) {
    constexpr int WSM = MT / 32;          // warps along M (4 or 2)
    constexpr int WSN = 8 / WSM;          // warps along N (2 or 4)
    constexpr int NFR = 64 / (WSN * 16);  // n-fragments per warp (2 or 1)
    constexpr int ASZ = MT * ASTR;

    const int z = blockIdx.z;
    const bf16* A = Ag + (size_t)z * sA;
    const bf16* B = Bg + (size_t)z * sB;
    const float* bi = bias ? bias + (size_t)z * sBias : nullptr;

    __shared__ __align__(16) char smem_raw[36864];
    bf16*  Abase = reinterpret_cast<bf16*>(smem_raw);
    bf16*  Bbase = Abase + 2 * ASZ;
    float* Cs    = reinterpret_cast<float*>(smem_raw);

    const int tid  = threadIdx.x;
    const int warp = tid >> 5;
    const int wm   = warp % WSM;
    const int wn   = warp / WSM;
    const int wnoff = wn * 16 * NFR;
    const int m0 = blockIdx.y * MT, n0 = blockIdx.x * 64;

    wmma::fragment<wmma::accumulator, 16, 16, 16, float> acc[2][NFR];
    #pragma unroll
    for (int i = 0; i < 2; i++)
        #pragma unroll
        for (int j = 0; j < NFR; j++) wmma::fill_fragment(acc[i][j], 0.f);

    auto load_stage = [&](int s, int k0) {
        bf16* As = Abase + s * ASZ;
        bf16* Bs = Bbase + s * BSZ;
        #pragma unroll
        for (int it = 0; it < MT / 64; it++) {
            int chunk = tid + it * 256;
            int r = chunk >> 2, c = (chunk & 3) << 3;
            cpa16(&As[r * ASTR + c], &A[(size_t)(m0 + r) * K + k0 + c]);
        }
        if (TB == 0) {
            int r = tid >> 3, c = (tid & 7) << 3;
            cpa16(&Bs[r * BSTR0 + c], &B[(size_t)(k0 + r) * N + n0 + c]);
        } else {
            int r = tid >> 2, c = (tid & 3) << 3;
            cpa16(&Bs[r * BSTR1 + c], &B[(size_t)(n0 + r) * K + k0 + c]);
        }
    };

    auto compute_stage = [&](int s) {
        bf16* As = Abase + s * ASZ;
        bf16* Bs = Bbase + s * BSZ;
        #pragma unroll
        for (int kk = 0; kk < 32; kk += 16) {
            wmma::fragment<wmma::matrix_a, 16, 16, 16, bf16, wmma::row_major> a0, a1;
            wmma::load_matrix_sync(a0, &As[(wm * 32 +  0) * ASTR + kk], ASTR);
            wmma::load_matrix_sync(a1, &As[(wm * 32 + 16) * ASTR + kk], ASTR);
            #pragma unroll
            for (int j = 0; j < NFR; j++) {
                if (TB == 0) {
                    wmma::fragment<wmma::matrix_b, 16, 16, 16, bf16, wmma::row_major> bf;
                    wmma::load_matrix_sync(bf, &Bs[kk * BSTR0 + wnoff + j * 16], BSTR0);
                    wmma::mma_sync(acc[0][j], a0, bf, acc[0][j]);
                    wmma::mma_sync(acc[1][j], a1, bf, acc[1][j]);
                } else {
                    wmma::fragment<wmma::matrix_b, 16, 16, 16, bf16, wmma::col_major> bf;
                    wmma::load_matrix_sync(bf, &Bs[(wnoff + j * 16) * BSTR1 + kk], BSTR1);
                    wmma::mma_sync(acc[0][j], a0, bf, acc[0][j]);
                    wmma::mma_sync(acc[1][j], a1, bf, acc[1][j]);
                }
            }
        }
    };

    const int KT = K >> 5;
    load_stage(0, 0);
    cpa_commit();
    for (int kt = 0; kt < KT; kt++) {
        if (kt + 1 < KT) { load_stage((kt + 1) & 1, (kt + 1) << 5); cpa_commit(); cpa_wait<1>(); }
        else             { cpa_wait<0>(); }
        __syncthreads();
        compute_stage(kt & 1);
        __syncthreads();
    }

    #pragma unroll
    for (int i = 0; i < 2; i++)
        #pragma unroll
        for (int j = 0; j < NFR; j++)
            wmma::store_matrix_sync(&Cs[(wm * 32 + i * 16) * 72 + wnoff + j * 16],
                                    acc[i][j], 72, wmma::mem_row_major);
    __syncthreads();

    #pragma unroll
    for (int it = 0; it < MT / 4; it++) {
        int idx = tid + it * 256;
        int r = idx >> 6, c = idx & 63;
        int m = m0 + r, n = n0 + c;
        float val = Cs[r * 72 + c];
        if (bi)   val += bi[n];
        if (relu) val = fmaxf(val, 0.f);
        if (OB) {
            reinterpret_cast<bf16*>(Cv)[(size_t)z * sC + (size_t)m * N + n] = __float2bfloat16(val);
        } else {
            float* C = reinterpret_cast<float*>(Cv) + (size_t)z * sC;
            if (res) val += res[(size_t)m * N + n];
            C[(size_t)m * N + n] = val;
        }
    }
}

// ---------------- fused flash attention ----------------
// grid: (TT/64, H, B), 256 threads. Q tile 64 queries; full K/V (128 keys).
// smem: Qs[64][72]b, Ks[128][72]b, Vs[128][72]b, S[64][132]f; Pb[64][136]b overlays Qs+Ks.
#define FA_SMEM 79872

__global__ __launch_bounds__(256) void flash_kernel(
        const bf16* __restrict__ Q, const bf16* __restrict__ Kp, const bf16* __restrict__ Vp,
        const int* __restrict__ toks, int causal, bf16* __restrict__ out) {
    extern __shared__ __align__(16) char sm[];
    bf16*  Qs = reinterpret_cast<bf16*>(sm);
    bf16*  Ks = Qs + 64 * 72;
    bf16*  Vs = Ks + 128 * 72;
    float* S  = reinterpret_cast<float*>(sm + 46080);
    bf16*  Pb = reinterpret_cast<bf16*>(sm);
    __shared__ int msk[TT];

    const int q0 = blockIdx.x * 64;
    const int h  = blockIdx.y;
    const int b  = blockIdx.z;
    const int tid = threadIdx.x, warp = tid >> 5, lane = tid & 31;

    for (int ch = tid; ch < 512; ch += 256) {
        int r = ch >> 3, c = (ch & 7) << 3;
        *reinterpret_cast<uint4*>(&Qs[r * 72 + c]) =
            *reinterpret_cast<const uint4*>(&Q[(size_t)(b * TT + q0 + r) * D + h * DK + c]);
    }
    for (int ch = tid; ch < 1024; ch += 256) {
        int r = ch >> 3, c = (ch & 7) << 3;
        *reinterpret_cast<uint4*>(&Ks[r * 72 + c]) =
            *reinterpret_cast<const uint4*>(&Kp[(size_t)(b * TT + r) * D + h * DK + c]);
        *reinterpret_cast<uint4*>(&Vs[r * 72 + c]) =
            *reinterpret_cast<const uint4*>(&Vp[(size_t)(b * TT + r) * D + h * DK + c]);
    }
    if (tid < TT) msk[tid] = (toks[b * TT + tid] == 1);
    __syncthreads();

    // S = Q @ K^T  (warp: wm=warp%4 rows, wn=warp/4 half of keys)
    {
        int wm = warp & 3, wn = warp >> 2;
        #pragma unroll
        for (int n = 0; n < 4; n++) {
            wmma::fragment<wmma::accumulator, 16, 16, 16, float> acc;
            wmma::fill_fragment(acc, 0.f);
            #pragma unroll
            for (int kk = 0; kk < 4; kk++) {
                wmma::fragment<wmma::matrix_a, 16, 16, 16, bf16, wmma::row_major> a;
                wmma::fragment<wmma::matrix_b, 16, 16, 16, bf16, wmma::col_major> bb;
                wmma::load_matrix_sync(a, &Qs[(wm * 16) * 72 + kk * 16], 72);
                wmma::load_matrix_sync(bb, &Ks[(wn * 64 + n * 16) * 72 + kk * 16], 72);
                wmma::mma_sync(acc, a, bb, acc);
            }
            wmma::store_matrix_sync(&S[(wm * 16) * 132 + wn * 64 + n * 16], acc, 132,
                                    wmma::mem_row_major);
        }
    }
    __syncthreads();

    // softmax: warp owns 8 rows; whole warp per row (32 lanes x 4 cols)
    for (int rr = 0; rr < 8; rr++) {
        int r = warp * 8 + rr;
        int qg = q0 + r;
        float v[4];
        #pragma unroll
        for (int j = 0; j < 4; j++) {
            int col = lane + j * 32;
            float s = S[r * 132 + col] * 0.125f;
            if (msk[col] || (causal && col > qg)) s = -1e30f;
            v[j] = s;
        }
        float m = fmaxf(fmaxf(v[0], v[1]), fmaxf(v[2], v[3]));
        #pragma unroll
        for (int o = 16; o; o >>= 1) m = fmaxf(m, __shfl_xor_sync(0xffffffffu, m, o));
        float e[4], sum = 0.f;
        #pragma unroll
        for (int j = 0; j < 4; j++) { e[j] = __expf(v[j] - m); sum += e[j]; }
        #pragma unroll
        for (int o = 16; o; o >>= 1) sum += __shfl_xor_sync(0xffffffffu, sum, o);
        float inv = __frcp_rn(sum);
        #pragma unroll
        for (int j = 0; j < 4; j++)
            Pb[r * 136 + lane + j * 32] = __float2bfloat16(e[j] * inv);
    }
    __syncthreads();

    // O = P @ V  (warp: wm=warp%4 rows, wn=warp/4 half of dims)
    {
        int wm = warp & 3, wn = warp >> 2;
        #pragma unroll
        for (int n = 0; n < 2; n++) {
            wmma::fragment<wmma::accumulator, 16, 16, 16, float> acc;
            wmma::fill_fragment(acc, 0.f);
            #pragma unroll
            for (int kk = 0; kk < 8; kk++) {
                wmma::fragment<wmma::matrix_a, 16, 16, 16, bf16, wmma::row_major> a;
                wmma::fragment<wmma::matrix_b, 16, 16, 16, bf16, wmma::row_major> bb;
                wmma::load_matrix_sync(a, &Pb[(wm * 16) * 136 + kk * 16], 136);
                wmma::load_matrix_sync(bb, &Vs[(kk * 16) * 72 + wn * 32 + n * 16], 72);
                wmma::mma_sync(acc, a, bb, acc);
            }
            wmma::store_matrix_sync(&S[(wm * 16) * 132 + wn * 32 + n * 16], acc, 132,
                                    wmma::mem_row_major);
        }
    }
    __syncthreads();

    for (int idx = tid; idx < 64 * 64; idx += 256) {
        int r = idx >> 6, c = idx & 63;
        out[(size_t)(b * TT + q0 + r) * D + h * DK + c] = __float2bfloat16(S[r * 132 + c]);
    }
}

// ---------------- log_softmax (online max+sum, then write) ----------------
__global__ __launch_bounds__(256) void logsoftmax_kernel(float* __restrict__ logits) {
    int row = blockIdx.x;
    float* x = logits + (size_t)row * VV;
    __shared__ float shm[256], shs[256];
    int tid = threadIdx.x;

    float m = -1e30f, s = 0.f;
    for (int i = tid; i < VV / 4; i += 256) {
        float4 v = reinterpret_cast<const float4*>(x)[i];
        float cm = fmaxf(fmaxf(v.x, v.y), fmaxf(v.z, v.w));
        if (cm > m) { s *= __expf(m - cm); m = cm; }
        s += __expf(v.x - m) + __expf(v.y - m) + __expf(v.z - m) + __expf(v.w - m);
    }
    shm[tid] = m; shs[tid] = s; __syncthreads();
    for (int o = 128; o; o >>= 1) {
        if (tid < o) {
            float m2 = shm[tid + o], s2 = shs[tid + o];
            float mn = fmaxf(shm[tid], m2);
            shs[tid] = shs[tid] * __expf(shm[tid] - mn) + s2 * __expf(m2 - mn);
            shm[tid] = mn;
        }
        __syncthreads();
    }
    float lse = shm[0] + logf(shs[0]);

    for (int i = tid; i < VV / 4; i += 256) {
        float4 v = reinterpret_cast<float4*>(x)[i];
        v.x -= lse; v.y -= lse; v.z -= lse; v.w -= lse;
        reinterpret_cast<float4*>(x)[i] = v;
    }
}

// ---------------- host helpers ----------------
static void G(const bf16* A, const bf16* B, const float* bias, const float* res,
              void* C, int M, int N, int K, int relu, int tb, int ob, int mt, int batch,
              size_t sA, size_t sB, size_t sBias, size_t sC) {
    dim3 grid(N / 64, M / mt, batch);
    if (tb)           wgemm<1, 0, 128><<<grid, 256>>>(A, B, bias, res, C, M, N, K, relu, sA, sB, sBias, sC);
    else if (ob && mt == 128) wgemm<0, 1, 128><<<grid, 256>>>(A, B, bias, res, C, M, N, K, relu, sA, sB, sBias, sC);
    else if (ob)      wgemm<0, 1, 64><<<grid, 256>>>(A, B, bias, res, C, M, N, K, relu, sA, sB, sBias, sC);
    else              wgemm<0, 0, 64><<<grid, 256>>>(A, B, bias, res, C, M, N, K, relu, sA, sB, sBias, sC);
}

static void CVT(const float* s, bf16* d, size_t n) {
    int n4 = (int)(n / 4);
    f2b_kernel<<<(n4 + 255) / 256, 256>>>(s, d, n4);
}

extern "C" void kernel_launch(void* const* d_in, const int* in_sizes, int n_in,
                              void* d_out, int out_size) {
    const int*   src        = (const int*)  d_in[0];
    const int*   tgt        = (const int*)  d_in[1];
    const float* tok_emb    = (const float*)d_in[2];
    const float* pos_emb    = (const float*)d_in[3];
    const float* enc_attn_w = (const float*)d_in[4];
    const float* enc_attn_b = (const float*)d_in[5];
    const float* enc_ffn_w1 = (const float*)d_in[6];
    const float* enc_ffn_b1 = (const float*)d_in[7];
    const float* enc_ffn_w2 = (const float*)d_in[8];
    const float* enc_ffn_b2 = (const float*)d_in[9];
    const float* enc_ln     = (const float*)d_in[10];
    const float* enc_fln    = (const float*)d_in[11];
    const float* dec_attn_w = (const float*)d_in[12];
    const float* dec_attn_b = (const float*)d_in[13];
    const float* dec_ffn_w1 = (const float*)d_in[14];
    const float* dec_ffn_b1 = (const float*)d_in[15];
    const float* dec_ffn_w2 = (const float*)d_in[16];
    const float* dec_ffn_b2 = (const float*)d_in[17];
    const float* dec_ln     = (const float*)d_in[18];
    const float* dec_fln    = (const float*)d_in[19];
    float* out = (float*)d_out;

    float *x;
    bf16 *qkv, *hb, *aob, *memb, *ffnb, *kc, *vc, *wp;
    cudaGetSymbolAddress((void**)&x,    g_x);
    cudaGetSymbolAddress((void**)&qkv,  g_qkv);
    cudaGetSymbolAddress((void**)&hb,   g_hb);
    cudaGetSymbolAddress((void**)&aob,  g_aob);
    cudaGetSymbolAddress((void**)&memb, g_memb);
    cudaGetSymbolAddress((void**)&ffnb, g_ffnb);
    cudaGetSymbolAddress((void**)&kc,   g_kc);
    cudaGetSymbolAddress((void**)&vc,   g_vc);
    cudaGetSymbolAddress((void**)&wp,   g_wpool);

    cudaFuncSetAttribute(flash_kernel, cudaFuncAttributeMaxDynamicSharedMemorySize, FA_SMEM);

    const size_t DD = (size_t)D * D;
    dim3 fgrid(TT / 64, H, BBATCH);

    CVT(enc_attn_w, wp + OFF_EA,  N_EA);
    CVT(enc_ffn_w1, wp + OFF_EF1, N_EF1);
    CVT(enc_ffn_w2, wp + OFF_EF2, N_EF2);
    CVT(dec_attn_w, wp + OFF_DA,  N_DA);
    CVT(dec_ffn_w1, wp + OFF_DF1, N_DF1);
    CVT(dec_ffn_w2, wp + OFF_DF2, N_DF2);
    CVT(tok_emb,    wp + OFF_EMB, N_EMB);

    // ================= encoder =================
    embed_kernel<<<(MROWS * D + 255) / 256, 256>>>(src, tok_emb, pos_emb, x);
    for (int i = 0; i < NL; i++) {
        const bf16*  W   = wp + OFF_EA + (size_t)i * 4 * DD;
        const float* Wb  = enc_attn_b + (size_t)i * 4 * D;
        const float* lnp = enc_ln + (size_t)i * 4 * D;

        ln_kernel<<<MROWS / 8, 256>>>(x, lnp, lnp + D, hb);
        G(hb, W, Wb, nullptr, qkv, MROWS, D, D, 0, 0, 1, 128, 3, 0, DD, D, MD);
        flash_kernel<<<fgrid, 256, FA_SMEM>>>(qkv, qkv + MD, qkv + 2 * MD, src, 0, aob);
        G(aob, W + 3 * DD, Wb + 3 * D, x, x, MROWS, D, D, 0, 0, 0, 64, 1, 0, 0, 0, 0);

        ln_kernel<<<MROWS / 8, 256>>>(x, lnp + 2 * D, lnp + 3 * D, hb);
        G(hb, wp + OFF_EF1 + (size_t)i * D * FF, enc_ffn_b1 + (size_t)i * FF,
          nullptr, ffnb, MROWS, FF, D, 1, 0, 1, 128, 1, 0, 0, 0, 0);
        G(ffnb, wp + OFF_EF2 + (size_t)i * FF * D, enc_ffn_b2 + (size_t)i * D,
          x, x, MROWS, D, FF, 0, 0, 0, 64, 1, 0, 0, 0, 0);
    }
    ln_kernel<<<MROWS / 8, 256>>>(x, enc_fln, enc_fln + D, memb);

    // cross-attention K/V for all decoder layers (batch over layers)
    G(memb, wp + OFF_DA + 5 * DD, dec_attn_b + 5 * D, nullptr, kc,
      MROWS, D, D, 0, 0, 1, 128, NL, 0, 8 * DD, 8 * D, MD);
    G(memb, wp + OFF_DA + 6 * DD, dec_attn_b + 6 * D, nullptr, vc,
      MROWS, D, D, 0, 0, 1, 128, NL, 0, 8 * DD, 8 * D, MD);

    // ================= decoder =================
    embed_kernel<<<(MROWS * D + 255) / 256, 256>>>(tgt, tok_emb, pos_emb, x);
    for (int i = 0; i < NL; i++) {
        const bf16*  W   = wp + OFF_DA + (size_t)i * 8 * DD;
        const float* Wb  = dec_attn_b + (size_t)i * 8 * D;
        const float* lnp = dec_ln + (size_t)i * 6 * D;

        // self-attention
        ln_kernel<<<MROWS / 8, 256>>>(x, lnp, lnp + D, hb);
        G(hb, W, Wb, nullptr, qkv, MROWS, D, D, 0, 0, 1, 128, 3, 0, DD, D, MD);
        flash_kernel<<<fgrid, 256, FA_SMEM>>>(qkv, qkv + MD, qkv + 2 * MD, tgt, 1, aob);
        G(aob, W + 3 * DD, Wb + 3 * D, x, x, MROWS, D, D, 0, 0, 0, 64, 1, 0, 0, 0, 0);

        // cross-attention
        ln_kernel<<<MROWS / 8, 256>>>(x, lnp + 2 * D, lnp + 3 * D, hb);
        G(hb, W + 4 * DD, Wb + 4 * D, nullptr, qkv, MROWS, D, D, 0, 0, 1, 64, 1, 0, 0, 0, 0);
        flash_kernel<<<fgrid, 256, FA_SMEM>>>(qkv, kc + (size_t)i * MD, vc + (size_t)i * MD,
                                              src, 0, aob);
        G(aob, W + 7 * DD, Wb + 7 * D, x, x, MROWS, D, D, 0, 0, 0, 64, 1, 0, 0, 0, 0);

        // FFN
        ln_kernel<<<MROWS / 8, 256>>>(x, lnp + 4 * D, lnp + 5 * D, hb);
        G(hb, wp + OFF_DF1 + (size_t)i * D * FF, dec_ffn_b1 + (size_t)i * FF,
          nullptr, ffnb, MROWS, FF, D, 1, 0, 1, 128, 1, 0, 0, 0, 0);
        G(ffnb, wp + OFF_DF2 + (size_t)i * FF * D, dec_ffn_b2 + (size_t)i * D,
          x, x, MROWS, D, FF, 0, 0, 0, 64, 1, 0, 0, 0, 0);
    }
    ln_kernel<<<MROWS / 8, 256>>>(x, dec_fln, dec_fln + D, hb);

    // ============ generator: tied projection + log_softmax ============
    G(hb, wp + OFF_EMB, nullptr, nullptr, out, MROWS, VV, D, 0, 1, 0, 128, 1, 0, 0, 0, 0);
    logsoftmax_kernel<<<MROWS, 256>>>(out);
}